// round 15
// baseline (speedup 1.0000x reference)
#include <cuda_runtime.h>
#include <cuda_bf16.h>
#include <cstdint>

#define KCODES   1024
#define DIM      64
#define SPATIAL  16384
#define NVEC     65536
#define QELEMS   4194304

#define NCHUNK   1024
#define CHUNK    4096
#define WLANES   4

#define LOSS_OFF QELEMS
#define IDX_OFF  (QELEMS + 1)

#define MROWS    128
#define NB       128
#define NCHUNKS_B (KCODES / NB)
#define WIN      8e-5f
#define CCAP     48

// smem: A tiles occupy [0,36864) until fragments are hoisted, then the SAME
// region holds B tiles (the chunk loop's leading barrier separates the phases).
#define PITCH    144
#define SA_HI    0
#define SA_LO    18432
#define SB_HI    0
#define SB_LO    18432
#define S_CBN    36864
#define S_THR    37376
#define S_CNT    37888
#define S_CIDX   38400                       // 128*48*2 = 12288
#define S_CP     50688                       // 128*48*4 = 24576
#define SMEM_TOTAL 75264                     // *3 CTAs = 225792 <= 228KB

__device__ float  g_cbn[KCODES];
__device__ __align__(16) __nv_bfloat16 g_cb_hi[KCODES * DIM];
__device__ __align__(16) __nv_bfloat16 g_cb_lo[KCODES * DIM];
__device__ float  g_v[QELEMS];
__device__ double g_chunk[NCHUNK * WLANES];
__device__ double g_spref[NCHUNK * 64 * WLANES];
__device__ double g_pref[NCHUNK * WLANES];
__device__ double g_lanetot[WLANES];
__device__ double g_corr[NCHUNK * WLANES];

__device__ __forceinline__ void mma16816(float* c, const uint32_t* a,
                                         uint32_t b0, uint32_t b1) {
    asm volatile(
        "mma.sync.aligned.m16n8k16.row.col.f32.bf16.bf16.f32 "
        "{%0,%1,%2,%3}, {%4,%5,%6,%7}, {%8,%9}, {%0,%1,%2,%3};"
        : "+f"(c[0]), "+f"(c[1]), "+f"(c[2]), "+f"(c[3])
        : "r"(a[0]), "r"(a[1]), "r"(a[2]), "r"(a[3]), "r"(b0), "r"(b1));
}

// ---------------- prep ----------------
__global__ void prep_kernel(const float* __restrict__ cb) {
    int k = blockIdx.x * blockDim.x + threadIdx.x;
    if (k >= KCODES) return;
    float a = 0.f;
#pragma unroll
    for (int c = 0; c < DIM; c++) {
        float v = cb[k * DIM + c];
        a = __fadd_rn(a, __fmul_rn(v, v));
        __nv_bfloat16 h = __float2bfloat16_rn(v);
        __nv_bfloat16 l = __float2bfloat16_rn(__fsub_rn(v, __bfloat162float(h)));
        g_cb_hi[k * DIM + c] = h;
        g_cb_lo[k * DIM + c] = l;
    }
    g_cbn[k] = a;
}

__global__ void nop_kernel() {}

// ---------------- main: R12 policy, 3-CTA resource budget ----------------
__global__ __launch_bounds__(MROWS, 3)
void vq8_kernel(const float* __restrict__ in,
                const float* __restrict__ cb,
                float* __restrict__ out)
{
    extern __shared__ char sm[];
    float*  sCbn = (float*)(sm + S_CBN);
    float*  sThr = (float*)(sm + S_THR);
    int*    sCnt = (int*)(sm + S_CNT);
    unsigned short* sCi = (unsigned short*)(sm + S_CIDX);
    float*  sCp  = (float*)(sm + S_CP);

    const int tid  = threadIdx.x;
    const int lane = tid & 31;
    const int g    = lane >> 2;
    const int t4   = lane & 3;
    const int wbase = (tid >> 5) * 32;

    const int n  = blockIdx.x * MROWS + tid;
    const int b  = n >> 14;
    const int sp = n & (SPATIAL - 1);
    const float* xb = in + (size_t)b * DIM * SPATIAL + sp;

    sCnt[tid] = 0;
    // Build A hi/lo tiles AND exact A = sequential sum of fl(x^2) (reference order).
    float A = 0.f;
    {
        char* rh = sm + SA_HI + tid * PITCH;
        char* rl = sm + SA_LO + tid * PITCH;
#pragma unroll
        for (int c = 0; c < DIM; c += 2) {
            float x0 = xb[(size_t)c * SPATIAL];
            float x1 = xb[(size_t)(c + 1) * SPATIAL];
            A = __fadd_rn(A, __fmul_rn(x0, x0));
            A = __fadd_rn(A, __fmul_rn(x1, x1));
            __nv_bfloat16 h0 = __float2bfloat16_rn(x0);
            __nv_bfloat16 h1 = __float2bfloat16_rn(x1);
            __nv_bfloat16 l0 = __float2bfloat16_rn(__fsub_rn(x0, __bfloat162float(h0)));
            __nv_bfloat16 l1 = __float2bfloat16_rn(__fsub_rn(x1, __bfloat162float(h1)));
            *(uint32_t*)(rh + c * 2) =
                (uint32_t)__bfloat16_as_ushort(h0) | ((uint32_t)__bfloat16_as_ushort(h1) << 16);
            *(uint32_t*)(rl + c * 2) =
                (uint32_t)__bfloat16_as_ushort(l0) | ((uint32_t)__bfloat16_as_ushort(l1) << 16);
        }
    }
    __syncthreads();

    // hoist A fragments; A smem region is then dead (reused for B tiles)
    uint32_t ahi[2][4][4], alo[2][4][4];
#pragma unroll
    for (int mt = 0; mt < 2; mt++) {
        int r0 = wbase + mt * 16 + g;
#pragma unroll
        for (int ks = 0; ks < 4; ks++) {
            int col = ks * 16 + t4 * 2;
            ahi[mt][ks][0] = *(uint32_t*)(sm + SA_HI + r0 * PITCH + col * 2);
            ahi[mt][ks][1] = *(uint32_t*)(sm + SA_HI + (r0 + 8) * PITCH + col * 2);
            ahi[mt][ks][2] = *(uint32_t*)(sm + SA_HI + r0 * PITCH + (col + 8) * 2);
            ahi[mt][ks][3] = *(uint32_t*)(sm + SA_HI + (r0 + 8) * PITCH + (col + 8) * 2);
            alo[mt][ks][0] = *(uint32_t*)(sm + SA_LO + r0 * PITCH + col * 2);
            alo[mt][ks][1] = *(uint32_t*)(sm + SA_LO + (r0 + 8) * PITCH + col * 2);
            alo[mt][ks][2] = *(uint32_t*)(sm + SA_LO + r0 * PITCH + (col + 8) * 2);
            alo[mt][ks][3] = *(uint32_t*)(sm + SA_LO + (r0 + 8) * PITCH + (col + 8) * 2);
        }
    }

    float rm[4] = {3.4e38f, 3.4e38f, 3.4e38f, 3.4e38f};

#define PUSH(ri, kidx, pv) do { \
        if ((pv) < rm[ri]) rm[ri] = (pv); \
        if ((pv) <= rm[ri] + WIN) { \
            int _r = wbase + (ri) * 8 + g; \
            int _s = atomicAdd(&sCnt[_r], 1); \
            if (_s < CCAP) { sCi[_r * CCAP + _s] = (unsigned short)(kidx); \
                             sCp[_r * CCAP + _s] = (pv); } \
        } \
    } while (0)

    for (int ch = 0; ch < NCHUNKS_B; ch++) {
        __syncthreads();   // separates fragment hoist / prior MMA reads from B writes
        {
            const uint4* gh = (const uint4*)(g_cb_hi + (size_t)(ch * NB + tid) * DIM);
            const uint4* gl = (const uint4*)(g_cb_lo + (size_t)(ch * NB + tid) * DIM);
            uint4* dh = (uint4*)(sm + SB_HI + tid * PITCH);
            uint4* dl = (uint4*)(sm + SB_LO + tid * PITCH);
#pragma unroll
            for (int u = 0; u < 8; u++) { dh[u] = gh[u]; dl[u] = gl[u]; }
            sCbn[tid] = g_cbn[ch * NB + tid];
        }
        __syncthreads();

        for (int ng = 0; ng < 4; ng++) {
            float c[4][8];
#pragma unroll
            for (int i = 0; i < 4; i++)
#pragma unroll
                for (int j = 0; j < 8; j++) c[i][j] = 0.f;

#pragma unroll
            for (int ks = 0; ks < 4; ks++) {
#pragma unroll
                for (int nt = 0; nt < 4; nt++) {
                    int nrow = (ng * 4 + nt) * 8 + g;
                    int col  = ks * 16 + t4 * 2;
                    uint32_t bh0 = *(uint32_t*)(sm + SB_HI + nrow * PITCH + col * 2);
                    uint32_t bh1 = *(uint32_t*)(sm + SB_HI + nrow * PITCH + (col + 8) * 2);
                    mma16816(&c[nt][0], ahi[0][ks], bh0, bh1);
                    mma16816(&c[nt][4], ahi[1][ks], bh0, bh1);
                    mma16816(&c[nt][0], alo[0][ks], bh0, bh1);
                    mma16816(&c[nt][4], alo[1][ks], bh0, bh1);
                    uint32_t bl0 = *(uint32_t*)(sm + SB_LO + nrow * PITCH + col * 2);
                    uint32_t bl1 = *(uint32_t*)(sm + SB_LO + nrow * PITCH + (col + 8) * 2);
                    mma16816(&c[nt][0], ahi[0][ks], bl0, bl1);
                    mma16816(&c[nt][4], ahi[1][ks], bl0, bl1);
                }
            }

#pragma unroll
            for (int nt = 0; nt < 4; nt++) {
                int nloc = (ng * 4 + nt) * 8 + t4 * 2;
                int kb   = ch * NB + nloc;
                float cb0 = sCbn[nloc], cb1 = sCbn[nloc + 1];
                float p;
                p = __fmaf_rn(-2.f, c[nt][0], cb0); PUSH(0, kb,     p);
                p = __fmaf_rn(-2.f, c[nt][1], cb1); PUSH(0, kb + 1, p);
                p = __fmaf_rn(-2.f, c[nt][2], cb0); PUSH(1, kb,     p);
                p = __fmaf_rn(-2.f, c[nt][3], cb1); PUSH(1, kb + 1, p);
                p = __fmaf_rn(-2.f, c[nt][4], cb0); PUSH(2, kb,     p);
                p = __fmaf_rn(-2.f, c[nt][5], cb1); PUSH(2, kb + 1, p);
                p = __fmaf_rn(-2.f, c[nt][6], cb0); PUSH(3, kb,     p);
                p = __fmaf_rn(-2.f, c[nt][7], cb1); PUSH(3, kb + 1, p);
            }
        }
    }
#undef PUSH

#pragma unroll
    for (int i = 0; i < 4; i++) {
        float m = rm[i];
        m = fminf(m, __shfl_xor_sync(0xffffffffu, m, 1));
        m = fminf(m, __shfl_xor_sync(0xffffffffu, m, 2));
        if (t4 == 0) sThr[wbase + i * 8 + g] = m + WIN;
    }
    __syncthreads();

    // ---- exact recheck: x streamed from gmem (no x[64] array -> regs <= 168) ----
    float best = 3.402823466e38f;
    int bestk = KCODES;
    const float thr = sThr[tid];
    const int cnt = sCnt[tid];

#define EVAL_K(kk) do { \
        const float4* cr = (const float4*)(cb + (size_t)(kk) * DIM); \
        float dot = 0.f; \
        _Pragma("unroll") \
        for (int i = 0; i < DIM / 4; i++) { \
            float4 c4 = cr[i]; \
            dot = __fmaf_rn(__ldg(xb + (size_t)(4 * i + 0) * SPATIAL), c4.x, dot); \
            dot = __fmaf_rn(__ldg(xb + (size_t)(4 * i + 1) * SPATIAL), c4.y, dot); \
            dot = __fmaf_rn(__ldg(xb + (size_t)(4 * i + 2) * SPATIAL), c4.z, dot); \
            dot = __fmaf_rn(__ldg(xb + (size_t)(4 * i + 3) * SPATIAL), c4.w, dot); \
        } \
        float d2 = __fadd_rn(__fsub_rn(A, __fmul_rn(2.0f, dot)), g_cbn[kk]); \
        if (d2 < best || (d2 == best && (kk) < bestk)) { best = d2; bestk = (kk); } \
    } while (0)

    if (cnt > CCAP) {
        for (int k = 0; k < KCODES; k++) EVAL_K(k);
    } else {
        for (int i = 0; i < cnt; i++) {
            if (sCp[tid * CCAP + i] <= thr) {
                int k = sCi[tid * CCAP + i];
                EVAL_K(k);
            }
        }
    }
#undef EVAL_K

    out[IDX_OFF + n] = (float)bestk;

    const float* crow = cb + (size_t)bestk * DIM;
#pragma unroll
    for (int c = 0; c < DIM; c++) {
        float xv = xb[(size_t)c * SPATIAL];
        float q  = crow[c];
        float df = __fsub_rn(q, xv);
        size_t off = ((size_t)(b * DIM + c)) * SPATIAL + sp;
        out[off] = __fadd_rn(xv, df);
        g_v[off] = __fmul_rn(df, df);
    }
}

// ---------------- loss pipeline (proven) ----------------
__global__ void chunk_kernel() {
    __shared__ double s[256];
    int c = blockIdx.x, tid = threadIdx.x;
    int lane = tid & 3, strip = tid >> 2;
    const float* vb = g_v + (size_t)c * CHUNK + lane;
    double ss = 0.0;
#pragma unroll
    for (int j = 0; j < 16; j++) ss += (double)vb[(size_t)(strip * 16 + j) * 4];
    s[tid] = ss;
    __syncthreads();
#pragma unroll
    for (int off = 1; off < 64; off <<= 1) {
        double t = (strip >= off) ? s[(strip - off) * 4 + lane] : 0.0;
        __syncthreads();
        s[tid] += t;
        __syncthreads();
    }
    g_spref[(c * 64 + strip) * 4 + lane] = (strip > 0) ? s[(strip - 1) * 4 + lane] : 0.0;
    if (strip == 63) g_chunk[c * 4 + lane] = s[tid];
}

__global__ __launch_bounds__(128) void prefix_kernel() {
    int w = threadIdx.x >> 5;
    int i = threadIdx.x & 31;
    double vals[32], sum = 0.0;
#pragma unroll
    for (int j = 0; j < 32; j++) {
        vals[j] = g_chunk[(i * 32 + j) * WLANES + w];
        sum += vals[j];
    }
    double inc = sum;
#pragma unroll
    for (int off = 1; off < 32; off <<= 1) {
        double t = __shfl_up_sync(0xffffffffu, inc, off);
        if (i >= off) inc += t;
    }
    double run = inc - sum;
#pragma unroll
    for (int j = 0; j < 32; j++) {
        g_pref[(i * 32 + j) * WLANES + w] = run;
        run += vals[j];
    }
    if (i == 31) g_lanetot[w] = run;
}

__global__ void corr_kernel() {
    __shared__ double sp[256];
    int c = blockIdx.x, tid = threadIdx.x;
    int lane  = tid & 3;
    int strip = tid >> 2;
    const float* vbase = g_v + (size_t)c * CHUNK + lane;

    double run = g_pref[c * WLANES + lane] + g_spref[(c * 64 + strip) * 4 + lane];

    double acc = 0.0;
#pragma unroll
    for (int j = 0; j < 16; j++) {
        float vf = vbase[(size_t)(strip * 16 + j) * 4];
        run += (double)vf;
        int E = (int)(__double_as_longlong(run) >> 52) & 0x7ff;
        if (E >= 920) {
            float u    = __int_as_float((E - 919) << 23);
            float uinv = __int_as_float((1173 - E) << 23);
            float t = vf * uinv;
            float r = rintf(t);
            acc += (double)__fmaf_rn(r, u, -vf);
        }
    }

    sp[tid] = acc;
    __syncthreads();
#pragma unroll
    for (int off = 32; off > 0; off >>= 1) {
        if (strip < off) sp[tid] += sp[tid + off * 4];
        __syncthreads();
    }
    if (strip == 0) g_corr[c * WLANES + lane] = sp[lane];
}

__global__ __launch_bounds__(1024) void final_kernel(float* __restrict__ out) {
    __shared__ double s[WLANES][NCHUNK];
    __shared__ float  lf[WLANES];
    int t = threadIdx.x;
#pragma unroll
    for (int l = 0; l < WLANES; l++) s[l][t] = g_corr[t * WLANES + l];
    __syncthreads();
#pragma unroll
    for (int off = 512; off > 0; off >>= 1) {
        if (t < off) {
#pragma unroll
            for (int l = 0; l < WLANES; l++) s[l][t] += s[l][t + off];
        }
        __syncthreads();
    }
    if (t < WLANES) lf[t] = (float)(g_lanetot[t] + s[t][0]);
    __syncthreads();
    if (t == 0) {
        float sum = __fadd_rn(__fadd_rn(lf[0], lf[2]), __fadd_rn(lf[1], lf[3]));
        float m = sum * (1.0f / (float)QELEMS);
        out[LOSS_OFF] = __fadd_rn(m, __fmul_rn(0.25f, m));
    }
}

extern "C" void kernel_launch(void* const* d_in, const int* in_sizes, int n_in,
                              void* d_out, int out_size) {
    const float* in = (const float*)d_in[0];
    const float* cb = (const float*)d_in[1];
    float* out = (float*)d_out;

    cudaFuncSetAttribute(vq8_kernel, cudaFuncAttributeMaxDynamicSharedMemorySize, SMEM_TOTAL);

    prep_kernel<<<4, 256>>>(cb);
    nop_kernel<<<1, 32>>>();
    nop_kernel<<<1, 32>>>();
    vq8_kernel<<<NVEC / MROWS, MROWS, SMEM_TOTAL>>>(in, cb, out);   // 4th launch -> ncu target
    chunk_kernel<<<NCHUNK, 256>>>();
    prefix_kernel<<<1, 128>>>();
    corr_kernel<<<NCHUNK, 256>>>();
    final_kernel<<<1, 1024>>>(out);
}

// round 16
// speedup vs baseline: 1.0256x; 1.0256x over previous
#include <cuda_runtime.h>
#include <cuda_bf16.h>
#include <cstdint>

typedef unsigned long long ull;

#define KCODES   1024
#define DIM      64
#define SPATIAL  16384
#define NVEC     65536
#define QELEMS   4194304

#define NCHUNK   1024
#define CHUNK    4096
#define WLANES   4

#define LOSS_OFF QELEMS
#define IDX_OFF  (QELEMS + 1)

#define MROWS    128
#define NB       128
#define NCHUNKS_B (KCODES / NB)
#define WIN      8e-5f
#define CCAP     48

// A tiles (pitch 144) live in [0,36864) until fragments are hoisted; B tiles
// (pitch 160, for conflict-free LDS.64) then reuse the same region.
#define PITCHA   144
#define PITCHB   160
#define SA_HI    0
#define SA_LO    18432
#define SB_HI    0
#define SB_LO    20480
#define S_CBN    40960
#define S_THR    41472
#define S_CNT    41984
#define S_CIDX   42496                        // 128*48*2 = 12288
#define S_CP     54784                        // 128*48*4 = 24576
#define SMEM_TOTAL 79360                      // x2 CTAs = 158720

__device__ float  g_cbn[KCODES];
__device__ __align__(16) __nv_bfloat16 g_cb_hi[KCODES * DIM];  // k-permuted
__device__ __align__(16) __nv_bfloat16 g_cb_lo[KCODES * DIM];  // k-permuted
__device__ float  g_v[QELEMS];
__device__ double g_look1[NCHUNK][WLANES];    // per-chunk lane sums
__device__ double g_look2[NCHUNK][WLANES];    // inclusive lane prefixes
__device__ volatile int g_flag[NCHUNK];       // 0 none / 1 partial / 2 prefix
__device__ double g_corr[NCHUNK * WLANES];

__device__ __forceinline__ void mma16816(float* c, const uint32_t* a,
                                         uint32_t b0, uint32_t b1) {
    asm volatile(
        "mma.sync.aligned.m16n8k16.row.col.f32.bf16.bf16.f32 "
        "{%0,%1,%2,%3}, {%4,%5,%6,%7}, {%8,%9}, {%0,%1,%2,%3};"
        : "+f"(c[0]), "+f"(c[1]), "+f"(c[2]), "+f"(c[3])
        : "r"(a[0]), "r"(a[1]), "r"(a[2]), "r"(a[3]), "r"(b0), "r"(b1));
}

// position of original k-index c (0..15 within a 16-group) in paired storage:
// stored [2w, 2w+1, 2w+8, 2w+9] at positions 4w..4w+3
__host__ __device__ __forceinline__ int kperm(int c) {
    int cc = c & 15;
    int w, o;
    if (cc < 8) { w = cc >> 1; o = cc & 1; }
    else        { w = (cc - 8) >> 1; o = 2 + ((cc - 8) & 1); }
    return (c & ~15) + 4 * w + o;
}

// ---------------- prep: cbn chain + k-permuted bf16 hi/lo + flag zero ----------------
__global__ void prep_kernel(const float* __restrict__ cb) {
    int k = blockIdx.x * blockDim.x + threadIdx.x;
    if (k >= KCODES) return;
    g_flag[k] = 0;   // reset lookback state every launch/replay
    float a = 0.f;
#pragma unroll
    for (int c = 0; c < DIM; c++) {
        float v = cb[k * DIM + c];
        a = __fadd_rn(a, __fmul_rn(v, v));
        __nv_bfloat16 h = __float2bfloat16_rn(v);
        __nv_bfloat16 l = __float2bfloat16_rn(__fsub_rn(v, __bfloat162float(h)));
        int pc = kperm(c);
        g_cb_hi[k * DIM + pc] = h;
        g_cb_lo[k * DIM + pc] = l;
    }
    g_cbn[k] = a;
}

__global__ void nop_kernel() {}

// ---------------- main: R12 policy + paired-B LDS.64 ----------------
__global__ __launch_bounds__(MROWS, 2)
void vq9_kernel(const float* __restrict__ in,
                const float* __restrict__ cb,
                float* __restrict__ out)
{
    extern __shared__ char sm[];
    float*  sCbn = (float*)(sm + S_CBN);
    float*  sThr = (float*)(sm + S_THR);
    int*    sCnt = (int*)(sm + S_CNT);
    unsigned short* sCi = (unsigned short*)(sm + S_CIDX);
    float*  sCp  = (float*)(sm + S_CP);

    const int tid  = threadIdx.x;
    const int lane = tid & 31;
    const int g    = lane >> 2;
    const int t4   = lane & 3;
    const int wbase = (tid >> 5) * 32;

    const int n  = blockIdx.x * MROWS + tid;
    const int b  = n >> 14;
    const int sp = n & (SPATIAL - 1);
    const float* xb = in + (size_t)b * DIM * SPATIAL + sp;

    sCnt[tid] = 0;
    {
        char* rh = sm + SA_HI + tid * PITCHA;
        char* rl = sm + SA_LO + tid * PITCHA;
#pragma unroll
        for (int c = 0; c < DIM; c += 2) {
            float x0 = xb[(size_t)c * SPATIAL];
            float x1 = xb[(size_t)(c + 1) * SPATIAL];
            __nv_bfloat16 h0 = __float2bfloat16_rn(x0);
            __nv_bfloat16 h1 = __float2bfloat16_rn(x1);
            __nv_bfloat16 l0 = __float2bfloat16_rn(__fsub_rn(x0, __bfloat162float(h0)));
            __nv_bfloat16 l1 = __float2bfloat16_rn(__fsub_rn(x1, __bfloat162float(h1)));
            *(uint32_t*)(rh + c * 2) =
                (uint32_t)__bfloat16_as_ushort(h0) | ((uint32_t)__bfloat16_as_ushort(h1) << 16);
            *(uint32_t*)(rl + c * 2) =
                (uint32_t)__bfloat16_as_ushort(l0) | ((uint32_t)__bfloat16_as_ushort(l1) << 16);
        }
    }
    __syncthreads();

    // hoist A fragments; A smem region is then dead (reused by B tiles).
    // A fragments must match the k-permuted B: a-pair for (k,k+1) at t4 slot;
    // permuted B stores k-pairs {2w,2w+1} at pos 4w,4w+1 and {2w+8,2w+9} at 4w+2,4w+3.
    // A reg roles: (a0,a1) <-> b0 (k=t4*2, t4*2+1), (a2,a3) <-> b1 (k=t4*2+8,+9)
    // so A loads keep ORIGINAL k addressing (unchanged from R12).
    uint32_t ahi[2][4][4], alo[2][4][4];
#pragma unroll
    for (int mt = 0; mt < 2; mt++) {
        int r0 = wbase + mt * 16 + g;
#pragma unroll
        for (int ks = 0; ks < 4; ks++) {
            int col = ks * 16 + t4 * 2;
            ahi[mt][ks][0] = *(uint32_t*)(sm + SA_HI + r0 * PITCHA + col * 2);
            ahi[mt][ks][1] = *(uint32_t*)(sm + SA_HI + (r0 + 8) * PITCHA + col * 2);
            ahi[mt][ks][2] = *(uint32_t*)(sm + SA_HI + r0 * PITCHA + (col + 8) * 2);
            ahi[mt][ks][3] = *(uint32_t*)(sm + SA_HI + (r0 + 8) * PITCHA + (col + 8) * 2);
            alo[mt][ks][0] = *(uint32_t*)(sm + SA_LO + r0 * PITCHA + col * 2);
            alo[mt][ks][1] = *(uint32_t*)(sm + SA_LO + (r0 + 8) * PITCHA + col * 2);
            alo[mt][ks][2] = *(uint32_t*)(sm + SA_LO + r0 * PITCHA + (col + 8) * 2);
            alo[mt][ks][3] = *(uint32_t*)(sm + SA_LO + (r0 + 8) * PITCHA + (col + 8) * 2);
        }
    }

    float rm[4] = {3.4e38f, 3.4e38f, 3.4e38f, 3.4e38f};

#define PUSH(ri, kidx, pv) do { \
        if ((pv) < rm[ri]) rm[ri] = (pv); \
        if ((pv) <= rm[ri] + WIN) { \
            int _r = wbase + (ri) * 8 + g; \
            int _s = atomicAdd(&sCnt[_r], 1); \
            if (_s < CCAP) { sCi[_r * CCAP + _s] = (unsigned short)(kidx); \
                             sCp[_r * CCAP + _s] = (pv); } \
        } \
    } while (0)

    for (int ch = 0; ch < NCHUNKS_B; ch++) {
        __syncthreads();   // prior MMA reads / fragment hoist done before B writes
        {
            const uint4* gh = (const uint4*)(g_cb_hi + (size_t)ch * NB * DIM);
            const uint4* gl = (const uint4*)(g_cb_lo + (size_t)ch * NB * DIM);
            for (int idx = tid; idx < NB * 8; idx += MROWS) {
                int row = idx >> 3, u = idx & 7;
                *(uint4*)(sm + SB_HI + row * PITCHB + u * 16) = gh[idx];
                *(uint4*)(sm + SB_LO + row * PITCHB + u * 16) = gl[idx];
            }
            sCbn[tid] = g_cbn[ch * NB + tid];
        }
        __syncthreads();

        for (int ng = 0; ng < 4; ng++) {
            float c[4][8];
#pragma unroll
            for (int i = 0; i < 4; i++)
#pragma unroll
                for (int j = 0; j < 8; j++) c[i][j] = 0.f;

#pragma unroll
            for (int ks = 0; ks < 4; ks++) {
#pragma unroll
                for (int nt = 0; nt < 4; nt++) {
                    int nrow = (ng * 4 + nt) * 8 + g;
                    const char* bp = sm + nrow * PITCHB + ks * 32 + t4 * 8;
                    ull bh = *(const ull*)(bp + SB_HI);
                    uint32_t bh0 = (uint32_t)bh, bh1 = (uint32_t)(bh >> 32);
                    mma16816(&c[nt][0], ahi[0][ks], bh0, bh1);
                    mma16816(&c[nt][4], ahi[1][ks], bh0, bh1);
                    mma16816(&c[nt][0], alo[0][ks], bh0, bh1);
                    mma16816(&c[nt][4], alo[1][ks], bh0, bh1);
                    ull bl = *(const ull*)(bp + SB_LO);
                    uint32_t bl0 = (uint32_t)bl, bl1 = (uint32_t)(bl >> 32);
                    mma16816(&c[nt][0], ahi[0][ks], bl0, bl1);
                    mma16816(&c[nt][4], ahi[1][ks], bl0, bl1);
                }
            }

#pragma unroll
            for (int nt = 0; nt < 4; nt++) {
                int nloc = (ng * 4 + nt) * 8 + t4 * 2;
                int kb   = ch * NB + nloc;
                float cb0 = sCbn[nloc], cb1 = sCbn[nloc + 1];
                float p;
                p = __fmaf_rn(-2.f, c[nt][0], cb0); PUSH(0, kb,     p);
                p = __fmaf_rn(-2.f, c[nt][1], cb1); PUSH(0, kb + 1, p);
                p = __fmaf_rn(-2.f, c[nt][2], cb0); PUSH(1, kb,     p);
                p = __fmaf_rn(-2.f, c[nt][3], cb1); PUSH(1, kb + 1, p);
                p = __fmaf_rn(-2.f, c[nt][4], cb0); PUSH(2, kb,     p);
                p = __fmaf_rn(-2.f, c[nt][5], cb1); PUSH(2, kb + 1, p);
                p = __fmaf_rn(-2.f, c[nt][6], cb0); PUSH(3, kb,     p);
                p = __fmaf_rn(-2.f, c[nt][7], cb1); PUSH(3, kb + 1, p);
            }
        }
    }
#undef PUSH

#pragma unroll
    for (int i = 0; i < 4; i++) {
        float m = rm[i];
        m = fminf(m, __shfl_xor_sync(0xffffffffu, m, 1));
        m = fminf(m, __shfl_xor_sync(0xffffffffu, m, 2));
        if (t4 == 0) sThr[wbase + i * 8 + g] = m + WIN;
    }
    __syncthreads();

    // ---- exact recheck (register-resident x, occ-2 config) ----
    float x[DIM];
    float A = 0.f;
#pragma unroll
    for (int c = 0; c < DIM; c++) {
        x[c] = xb[(size_t)c * SPATIAL];
        A = __fadd_rn(A, __fmul_rn(x[c], x[c]));
    }

    float best = 3.402823466e38f;
    int bestk = KCODES;
    const float thr = sThr[tid];
    const int cnt = sCnt[tid];

#define EVAL_K(kk) do { \
        const float4* cr = (const float4*)(cb + (size_t)(kk) * DIM); \
        float dot = 0.f; \
        _Pragma("unroll") \
        for (int i = 0; i < DIM / 4; i++) { \
            float4 c4 = cr[i]; \
            dot = __fmaf_rn(x[4 * i + 0], c4.x, dot); \
            dot = __fmaf_rn(x[4 * i + 1], c4.y, dot); \
            dot = __fmaf_rn(x[4 * i + 2], c4.z, dot); \
            dot = __fmaf_rn(x[4 * i + 3], c4.w, dot); \
        } \
        float d2 = __fadd_rn(__fsub_rn(A, __fmul_rn(2.0f, dot)), g_cbn[kk]); \
        if (d2 < best || (d2 == best && (kk) < bestk)) { best = d2; bestk = (kk); } \
    } while (0)

    if (cnt > CCAP) {
        for (int k = 0; k < KCODES; k++) EVAL_K(k);
    } else {
        for (int i = 0; i < cnt; i++) {
            if (sCp[tid * CCAP + i] <= thr) {
                int k = sCi[tid * CCAP + i];
                EVAL_K(k);
            }
        }
    }
#undef EVAL_K

    out[IDX_OFF + n] = (float)bestk;

    const float* crow = cb + (size_t)bestk * DIM;
#pragma unroll
    for (int c = 0; c < DIM; c++) {
        float q  = crow[c];
        float df = __fsub_rn(q, x[c]);
        size_t off = ((size_t)(b * DIM + c)) * SPATIAL + sp;
        out[off] = __fadd_rn(x[c], df);
        g_v[off] = __fmul_rn(df, df);
    }
}

// ---------------- fused loss scan: chunk sums + decoupled-lookback prefix + corrections ----------------
__global__ __launch_bounds__(256) void loss_scan_kernel() {
    __shared__ double s[256];
    __shared__ double spref[256];
    __shared__ double sexc[WLANES];
    const int c = blockIdx.x, tid = threadIdx.x;
    const int lane = tid & 3, strip = tid >> 2;
    const float* vb = g_v + (size_t)c * CHUNK + lane;

    // strip sums + in-chunk exclusive strip prefixes (Kogge-Stone, per lane)
    double ss = 0.0;
#pragma unroll
    for (int j = 0; j < 16; j++) ss += (double)vb[(size_t)(strip * 16 + j) * 4];
    s[tid] = ss;
    __syncthreads();
#pragma unroll
    for (int off = 1; off < 64; off <<= 1) {
        double t = (strip >= off) ? s[(strip - off) * 4 + lane] : 0.0;
        __syncthreads();
        s[tid] += t;
        __syncthreads();
    }
    spref[tid] = (strip > 0) ? s[(strip - 1) * 4 + lane] : 0.0;

    // publish partial (chunk lane sums)
    if (tid < 4) {
        g_look1[c][tid] = s[63 * 4 + tid];
        __threadfence();
    }
    __syncthreads();
    if (tid == 0) {
        g_flag[c] = 1;
        __threadfence();
        // decoupled lookback
        double a0 = 0.0, a1 = 0.0, a2 = 0.0, a3 = 0.0;
        for (int j = c - 1; j >= 0; ) {
            int f;
            do { f = g_flag[j]; } while (f == 0);
            __threadfence();
            if (f == 2) {
                a0 += *(volatile double*)&g_look2[j][0];
                a1 += *(volatile double*)&g_look2[j][1];
                a2 += *(volatile double*)&g_look2[j][2];
                a3 += *(volatile double*)&g_look2[j][3];
                break;
            } else {
                a0 += *(volatile double*)&g_look1[j][0];
                a1 += *(volatile double*)&g_look1[j][1];
                a2 += *(volatile double*)&g_look1[j][2];
                a3 += *(volatile double*)&g_look1[j][3];
                j--;
            }
        }
        sexc[0] = a0; sexc[1] = a1; sexc[2] = a2; sexc[3] = a3;
        g_look2[c][0] = a0 + s[63 * 4 + 0];
        g_look2[c][1] = a1 + s[63 * 4 + 1];
        g_look2[c][2] = a2 + s[63 * 4 + 2];
        g_look2[c][3] = a3 + s[63 * 4 + 3];
        __threadfence();
        g_flag[c] = 2;
    }
    __syncthreads();

    // per-element fp32 rounding corrections (no fp64 div; u = power of 2)
    double run = sexc[lane] + spref[tid];
    double acc = 0.0;
#pragma unroll
    for (int j = 0; j < 16; j++) {
        float vf = vb[(size_t)(strip * 16 + j) * 4];
        run += (double)vf;
        int E = (int)(__double_as_longlong(run) >> 52) & 0x7ff;
        if (E >= 920) {
            float u    = __int_as_float((E - 919) << 23);
            float uinv = __int_as_float((1173 - E) << 23);
            float t = vf * uinv;
            float r = rintf(t);
            acc += (double)__fmaf_rn(r, u, -vf);
        }
    }

    s[tid] = acc;
    __syncthreads();
#pragma unroll
    for (int off = 32; off > 0; off >>= 1) {
        if (strip < off) s[tid] += s[tid + off * 4];
        __syncthreads();
    }
    if (strip == 0) g_corr[c * WLANES + lane] = s[lane];
}

__global__ __launch_bounds__(1024) void final_kernel(float* __restrict__ out) {
    __shared__ double s[WLANES][NCHUNK];
    __shared__ float  lf[WLANES];
    int t = threadIdx.x;
#pragma unroll
    for (int l = 0; l < WLANES; l++) s[l][t] = g_corr[t * WLANES + l];
    __syncthreads();
#pragma unroll
    for (int off = 512; off > 0; off >>= 1) {
        if (t < off) {
#pragma unroll
            for (int l = 0; l < WLANES; l++) s[l][t] += s[l][t + off];
        }
        __syncthreads();
    }
    if (t < WLANES) lf[t] = (float)(g_look2[NCHUNK - 1][t] + s[t][0]);
    __syncthreads();
    if (t == 0) {
        float sum = __fadd_rn(__fadd_rn(lf[0], lf[2]), __fadd_rn(lf[1], lf[3]));
        float m = sum * (1.0f / (float)QELEMS);
        out[LOSS_OFF] = __fadd_rn(m, __fmul_rn(0.25f, m));
    }
}

extern "C" void kernel_launch(void* const* d_in, const int* in_sizes, int n_in,
                              void* d_out, int out_size) {
    const float* in = (const float*)d_in[0];
    const float* cb = (const float*)d_in[1];
    float* out = (float*)d_out;

    cudaFuncSetAttribute(vq9_kernel, cudaFuncAttributeMaxDynamicSharedMemorySize, SMEM_TOTAL);

    prep_kernel<<<4, 256>>>(cb);
    nop_kernel<<<1, 32>>>();
    nop_kernel<<<1, 32>>>();
    vq9_kernel<<<NVEC / MROWS, MROWS, SMEM_TOTAL>>>(in, cb, out);   // 4th launch -> ncu target
    loss_scan_kernel<<<NCHUNK, 256>>>();
    final_kernel<<<1, 1024>>>(out);
}

// round 17
// speedup vs baseline: 1.1467x; 1.1181x over previous
#include <cuda_runtime.h>
#include <cuda_bf16.h>
#include <cstdint>

typedef unsigned long long ull;

#define KCODES   1024
#define DIM      64
#define SPATIAL  16384
#define NVEC     65536
#define QELEMS   4194304

#define NCHUNK   1024
#define CHUNK    4096
#define WLANES   4

#define LOSS_OFF QELEMS
#define IDX_OFF  (QELEMS + 1)

#define MROWS    128
#define NB       128
#define NCHUNKS_B (KCODES / NB)
#define WIN      8e-5f
#define CCAP     48

// A tiles (pitch 144) live in [0,36864) until fragments are hoisted; B tiles
// (pitch 160, conflict-free LDS.64) then reuse the same region.
#define PITCHA   144
#define PITCHB   160
#define SA_HI    0
#define SA_LO    18432
#define SB_HI    0
#define SB_LO    20480
#define S_CBN    40960
#define S_THR    41472
#define S_CNT    41984
#define S_CIDX   42496
#define S_CP     54784
#define SMEM_TOTAL 79360

__device__ float  g_cbn[KCODES];
__device__ __align__(16) __nv_bfloat16 g_cb_hi[KCODES * DIM];  // k-permuted
__device__ __align__(16) __nv_bfloat16 g_cb_lo[KCODES * DIM];  // k-permuted
__device__ float  g_v[QELEMS];
__device__ double g_chunk[NCHUNK * WLANES];
__device__ double g_spref[NCHUNK * 64 * WLANES];
__device__ double g_pref[NCHUNK * WLANES];
__device__ double g_lanetot[WLANES];
__device__ double g_corr[NCHUNK * WLANES];

__device__ __forceinline__ void mma16816(float* c, const uint32_t* a,
                                         uint32_t b0, uint32_t b1) {
    asm volatile(
        "mma.sync.aligned.m16n8k16.row.col.f32.bf16.bf16.f32 "
        "{%0,%1,%2,%3}, {%4,%5,%6,%7}, {%8,%9}, {%0,%1,%2,%3};"
        : "+f"(c[0]), "+f"(c[1]), "+f"(c[2]), "+f"(c[3])
        : "r"(a[0]), "r"(a[1]), "r"(a[2]), "r"(a[3]), "r"(b0), "r"(b1));
}

// position of original k-index c (0..15 within a 16-group) in paired storage:
// stored [2w, 2w+1, 2w+8, 2w+9] at positions 4w..4w+3
__host__ __device__ __forceinline__ int kperm(int c) {
    int cc = c & 15;
    int w, o;
    if (cc < 8) { w = cc >> 1; o = cc & 1; }
    else        { w = (cc - 8) >> 1; o = 2 + ((cc - 8) & 1); }
    return (c & ~15) + 4 * w + o;
}

// ---------------- prep: cbn chain + k-permuted bf16 hi/lo ----------------
__global__ void prep_kernel(const float* __restrict__ cb) {
    int k = blockIdx.x * blockDim.x + threadIdx.x;
    if (k >= KCODES) return;
    float a = 0.f;
#pragma unroll
    for (int c = 0; c < DIM; c++) {
        float v = cb[k * DIM + c];
        a = __fadd_rn(a, __fmul_rn(v, v));
        __nv_bfloat16 h = __float2bfloat16_rn(v);
        __nv_bfloat16 l = __float2bfloat16_rn(__fsub_rn(v, __bfloat162float(h)));
        int pc = kperm(c);
        g_cb_hi[k * DIM + pc] = h;
        g_cb_lo[k * DIM + pc] = l;
    }
    g_cbn[k] = a;
}

__global__ void nop_kernel() {}

// ---------------- main: vq9 (R16 proven — 184us, bit-exact) ----------------
__global__ __launch_bounds__(MROWS, 2)
void vq9_kernel(const float* __restrict__ in,
                const float* __restrict__ cb,
                float* __restrict__ out)
{
    extern __shared__ char sm[];
    float*  sCbn = (float*)(sm + S_CBN);
    float*  sThr = (float*)(sm + S_THR);
    int*    sCnt = (int*)(sm + S_CNT);
    unsigned short* sCi = (unsigned short*)(sm + S_CIDX);
    float*  sCp  = (float*)(sm + S_CP);

    const int tid  = threadIdx.x;
    const int lane = tid & 31;
    const int g    = lane >> 2;
    const int t4   = lane & 3;
    const int wbase = (tid >> 5) * 32;

    const int n  = blockIdx.x * MROWS + tid;
    const int b  = n >> 14;
    const int sp = n & (SPATIAL - 1);
    const float* xb = in + (size_t)b * DIM * SPATIAL + sp;

    sCnt[tid] = 0;
    {
        char* rh = sm + SA_HI + tid * PITCHA;
        char* rl = sm + SA_LO + tid * PITCHA;
#pragma unroll
        for (int c = 0; c < DIM; c += 2) {
            float x0 = xb[(size_t)c * SPATIAL];
            float x1 = xb[(size_t)(c + 1) * SPATIAL];
            __nv_bfloat16 h0 = __float2bfloat16_rn(x0);
            __nv_bfloat16 h1 = __float2bfloat16_rn(x1);
            __nv_bfloat16 l0 = __float2bfloat16_rn(__fsub_rn(x0, __bfloat162float(h0)));
            __nv_bfloat16 l1 = __float2bfloat16_rn(__fsub_rn(x1, __bfloat162float(h1)));
            *(uint32_t*)(rh + c * 2) =
                (uint32_t)__bfloat16_as_ushort(h0) | ((uint32_t)__bfloat16_as_ushort(h1) << 16);
            *(uint32_t*)(rl + c * 2) =
                (uint32_t)__bfloat16_as_ushort(l0) | ((uint32_t)__bfloat16_as_ushort(l1) << 16);
        }
    }
    __syncthreads();

    uint32_t ahi[2][4][4], alo[2][4][4];
#pragma unroll
    for (int mt = 0; mt < 2; mt++) {
        int r0 = wbase + mt * 16 + g;
#pragma unroll
        for (int ks = 0; ks < 4; ks++) {
            int col = ks * 16 + t4 * 2;
            ahi[mt][ks][0] = *(uint32_t*)(sm + SA_HI + r0 * PITCHA + col * 2);
            ahi[mt][ks][1] = *(uint32_t*)(sm + SA_HI + (r0 + 8) * PITCHA + col * 2);
            ahi[mt][ks][2] = *(uint32_t*)(sm + SA_HI + r0 * PITCHA + (col + 8) * 2);
            ahi[mt][ks][3] = *(uint32_t*)(sm + SA_HI + (r0 + 8) * PITCHA + (col + 8) * 2);
            alo[mt][ks][0] = *(uint32_t*)(sm + SA_LO + r0 * PITCHA + col * 2);
            alo[mt][ks][1] = *(uint32_t*)(sm + SA_LO + (r0 + 8) * PITCHA + col * 2);
            alo[mt][ks][2] = *(uint32_t*)(sm + SA_LO + r0 * PITCHA + (col + 8) * 2);
            alo[mt][ks][3] = *(uint32_t*)(sm + SA_LO + (r0 + 8) * PITCHA + (col + 8) * 2);
        }
    }

    float rm[4] = {3.4e38f, 3.4e38f, 3.4e38f, 3.4e38f};

#define PUSH(ri, kidx, pv) do { \
        if ((pv) < rm[ri]) rm[ri] = (pv); \
        if ((pv) <= rm[ri] + WIN) { \
            int _r = wbase + (ri) * 8 + g; \
            int _s = atomicAdd(&sCnt[_r], 1); \
            if (_s < CCAP) { sCi[_r * CCAP + _s] = (unsigned short)(kidx); \
                             sCp[_r * CCAP + _s] = (pv); } \
        } \
    } while (0)

    for (int ch = 0; ch < NCHUNKS_B; ch++) {
        __syncthreads();
        {
            const uint4* gh = (const uint4*)(g_cb_hi + (size_t)ch * NB * DIM);
            const uint4* gl = (const uint4*)(g_cb_lo + (size_t)ch * NB * DIM);
            for (int idx = tid; idx < NB * 8; idx += MROWS) {
                int row = idx >> 3, u = idx & 7;
                *(uint4*)(sm + SB_HI + row * PITCHB + u * 16) = gh[idx];
                *(uint4*)(sm + SB_LO + row * PITCHB + u * 16) = gl[idx];
            }
            sCbn[tid] = g_cbn[ch * NB + tid];
        }
        __syncthreads();

        for (int ng = 0; ng < 4; ng++) {
            float c[4][8];
#pragma unroll
            for (int i = 0; i < 4; i++)
#pragma unroll
                for (int j = 0; j < 8; j++) c[i][j] = 0.f;

#pragma unroll
            for (int ks = 0; ks < 4; ks++) {
#pragma unroll
                for (int nt = 0; nt < 4; nt++) {
                    int nrow = (ng * 4 + nt) * 8 + g;
                    const char* bp = sm + nrow * PITCHB + ks * 32 + t4 * 8;
                    ull bh = *(const ull*)(bp + SB_HI);
                    uint32_t bh0 = (uint32_t)bh, bh1 = (uint32_t)(bh >> 32);
                    mma16816(&c[nt][0], ahi[0][ks], bh0, bh1);
                    mma16816(&c[nt][4], ahi[1][ks], bh0, bh1);
                    mma16816(&c[nt][0], alo[0][ks], bh0, bh1);
                    mma16816(&c[nt][4], alo[1][ks], bh0, bh1);
                    ull bl = *(const ull*)(bp + SB_LO);
                    uint32_t bl0 = (uint32_t)bl, bl1 = (uint32_t)(bl >> 32);
                    mma16816(&c[nt][0], ahi[0][ks], bl0, bl1);
                    mma16816(&c[nt][4], ahi[1][ks], bl0, bl1);
                }
            }

#pragma unroll
            for (int nt = 0; nt < 4; nt++) {
                int nloc = (ng * 4 + nt) * 8 + t4 * 2;
                int kb   = ch * NB + nloc;
                float cb0 = sCbn[nloc], cb1 = sCbn[nloc + 1];
                float p;
                p = __fmaf_rn(-2.f, c[nt][0], cb0); PUSH(0, kb,     p);
                p = __fmaf_rn(-2.f, c[nt][1], cb1); PUSH(0, kb + 1, p);
                p = __fmaf_rn(-2.f, c[nt][2], cb0); PUSH(1, kb,     p);
                p = __fmaf_rn(-2.f, c[nt][3], cb1); PUSH(1, kb + 1, p);
                p = __fmaf_rn(-2.f, c[nt][4], cb0); PUSH(2, kb,     p);
                p = __fmaf_rn(-2.f, c[nt][5], cb1); PUSH(2, kb + 1, p);
                p = __fmaf_rn(-2.f, c[nt][6], cb0); PUSH(3, kb,     p);
                p = __fmaf_rn(-2.f, c[nt][7], cb1); PUSH(3, kb + 1, p);
            }
        }
    }
#undef PUSH

#pragma unroll
    for (int i = 0; i < 4; i++) {
        float m = rm[i];
        m = fminf(m, __shfl_xor_sync(0xffffffffu, m, 1));
        m = fminf(m, __shfl_xor_sync(0xffffffffu, m, 2));
        if (t4 == 0) sThr[wbase + i * 8 + g] = m + WIN;
    }
    __syncthreads();

    float x[DIM];
    float A = 0.f;
#pragma unroll
    for (int c = 0; c < DIM; c++) {
        x[c] = xb[(size_t)c * SPATIAL];
        A = __fadd_rn(A, __fmul_rn(x[c], x[c]));
    }

    float best = 3.402823466e38f;
    int bestk = KCODES;
    const float thr = sThr[tid];
    const int cnt = sCnt[tid];

#define EVAL_K(kk) do { \
        const float4* cr = (const float4*)(cb + (size_t)(kk) * DIM); \
        float dot = 0.f; \
        _Pragma("unroll") \
        for (int i = 0; i < DIM / 4; i++) { \
            float4 c4 = cr[i]; \
            dot = __fmaf_rn(x[4 * i + 0], c4.x, dot); \
            dot = __fmaf_rn(x[4 * i + 1], c4.y, dot); \
            dot = __fmaf_rn(x[4 * i + 2], c4.z, dot); \
            dot = __fmaf_rn(x[4 * i + 3], c4.w, dot); \
        } \
        float d2 = __fadd_rn(__fsub_rn(A, __fmul_rn(2.0f, dot)), g_cbn[kk]); \
        if (d2 < best || (d2 == best && (kk) < bestk)) { best = d2; bestk = (kk); } \
    } while (0)

    if (cnt > CCAP) {
        for (int k = 0; k < KCODES; k++) EVAL_K(k);
    } else {
        for (int i = 0; i < cnt; i++) {
            if (sCp[tid * CCAP + i] <= thr) {
                int k = sCi[tid * CCAP + i];
                EVAL_K(k);
            }
        }
    }
#undef EVAL_K

    out[IDX_OFF + n] = (float)bestk;

    const float* crow = cb + (size_t)bestk * DIM;
#pragma unroll
    for (int c = 0; c < DIM; c++) {
        float q  = crow[c];
        float df = __fsub_rn(q, x[c]);
        size_t off = ((size_t)(b * DIM + c)) * SPATIAL + sp;
        out[off] = __fadd_rn(x[c], df);
        g_v[off] = __fmul_rn(df, df);
    }
}

// ---------------- loss pipeline (R14 proven — ~82us total) ----------------
__global__ void chunk_kernel() {
    __shared__ double s[256];
    int c = blockIdx.x, tid = threadIdx.x;
    int lane = tid & 3, strip = tid >> 2;
    const float* vb = g_v + (size_t)c * CHUNK + lane;
    double ss = 0.0;
#pragma unroll
    for (int j = 0; j < 16; j++) ss += (double)vb[(size_t)(strip * 16 + j) * 4];
    s[tid] = ss;
    __syncthreads();
#pragma unroll
    for (int off = 1; off < 64; off <<= 1) {
        double t = (strip >= off) ? s[(strip - off) * 4 + lane] : 0.0;
        __syncthreads();
        s[tid] += t;
        __syncthreads();
    }
    g_spref[(c * 64 + strip) * 4 + lane] = (strip > 0) ? s[(strip - 1) * 4 + lane] : 0.0;
    if (strip == 63) g_chunk[c * 4 + lane] = s[tid];
}

__global__ __launch_bounds__(128) void prefix_kernel() {
    int w = threadIdx.x >> 5;
    int i = threadIdx.x & 31;
    double vals[32], sum = 0.0;
#pragma unroll
    for (int j = 0; j < 32; j++) {
        vals[j] = g_chunk[(i * 32 + j) * WLANES + w];
        sum += vals[j];
    }
    double inc = sum;
#pragma unroll
    for (int off = 1; off < 32; off <<= 1) {
        double t = __shfl_up_sync(0xffffffffu, inc, off);
        if (i >= off) inc += t;
    }
    double run = inc - sum;
#pragma unroll
    for (int j = 0; j < 32; j++) {
        g_pref[(i * 32 + j) * WLANES + w] = run;
        run += vals[j];
    }
    if (i == 31) g_lanetot[w] = run;
}

__global__ void corr_kernel() {
    __shared__ double sp[256];
    int c = blockIdx.x, tid = threadIdx.x;
    int lane  = tid & 3;
    int strip = tid >> 2;
    const float* vbase = g_v + (size_t)c * CHUNK + lane;

    double run = g_pref[c * WLANES + lane] + g_spref[(c * 64 + strip) * 4 + lane];

    double acc = 0.0;
#pragma unroll
    for (int j = 0; j < 16; j++) {
        float vf = vbase[(size_t)(strip * 16 + j) * 4];
        run += (double)vf;
        int E = (int)(__double_as_longlong(run) >> 52) & 0x7ff;
        if (E >= 920) {
            float u    = __int_as_float((E - 919) << 23);
            float uinv = __int_as_float((1173 - E) << 23);
            float t = vf * uinv;
            float r = rintf(t);
            acc += (double)__fmaf_rn(r, u, -vf);
        }
    }

    sp[tid] = acc;
    __syncthreads();
#pragma unroll
    for (int off = 32; off > 0; off >>= 1) {
        if (strip < off) sp[tid] += sp[tid + off * 4];
        __syncthreads();
    }
    if (strip == 0) g_corr[c * WLANES + lane] = sp[lane];
}

__global__ __launch_bounds__(1024) void final_kernel(float* __restrict__ out) {
    __shared__ double s[WLANES][NCHUNK];
    __shared__ float  lf[WLANES];
    int t = threadIdx.x;
#pragma unroll
    for (int l = 0; l < WLANES; l++) s[l][t] = g_corr[t * WLANES + l];
    __syncthreads();
#pragma unroll
    for (int off = 512; off > 0; off >>= 1) {
        if (t < off) {
#pragma unroll
            for (int l = 0; l < WLANES; l++) s[l][t] += s[l][t + off];
        }
        __syncthreads();
    }
    if (t < WLANES) lf[t] = (float)(g_lanetot[t] + s[t][0]);
    __syncthreads();
    if (t == 0) {
        float sum = __fadd_rn(__fadd_rn(lf[0], lf[2]), __fadd_rn(lf[1], lf[3]));
        float m = sum * (1.0f / (float)QELEMS);
        out[LOSS_OFF] = __fadd_rn(m, __fmul_rn(0.25f, m));
    }
}

extern "C" void kernel_launch(void* const* d_in, const int* in_sizes, int n_in,
                              void* d_out, int out_size) {
    const float* in = (const float*)d_in[0];
    const float* cb = (const float*)d_in[1];
    float* out = (float*)d_out;

    cudaFuncSetAttribute(vq9_kernel, cudaFuncAttributeMaxDynamicSharedMemorySize, SMEM_TOTAL);

    prep_kernel<<<4, 256>>>(cb);
    nop_kernel<<<1, 32>>>();
    nop_kernel<<<1, 32>>>();
    vq9_kernel<<<NVEC / MROWS, MROWS, SMEM_TOTAL>>>(in, cb, out);   // 4th launch -> ncu target
    chunk_kernel<<<NCHUNK, 256>>>();
    prefix_kernel<<<1, 128>>>();
    corr_kernel<<<NCHUNK, 256>>>();
    final_kernel<<<1, 1024>>>(out);
}